// round 1
// baseline (speedup 1.0000x reference)
#include <cuda_runtime.h>

// ---------------------------------------------------------------------------
// FermiLayer: N=512 (256 up / 256 dn), SINGLE=256, PAIR=128
// inputs: [0] h_one (512,256) [1] h_two (512,512,128) [2] W1 (512,256)
//         [3] b1 (256) [4] Wg (512,256) [5] W2 (128,128) [6] b2 (128)
// output: [h_one_out (512*256) | h_two_out (512*512*128)] fp32
// ---------------------------------------------------------------------------

#define GAIN    1.5927812698663017f
#define RSQRT2  0.7071067811865475f
#define INV256  0.00390625f

// scratch (allocation-free rule: __device__ globals)
__device__ float g_g2[2 * 512 * 128];  // per-spin mean over senders: [spin][j][p]
__device__ float g_g1[512];            // [g1_up(256) | g1_dn(256)]

// ---------------------------------------------------------------------------
// K1a: g1[s*256+c] = mean over 256 rows of h_one for spin s
// ---------------------------------------------------------------------------
__global__ void k_g1(const float* __restrict__ h_one) {
    int s = blockIdx.x;          // 0..1
    int c = threadIdx.x;         // 0..255
    const float* p = h_one + (size_t)s * 256 * 256 + c;
    float sum = 0.f;
#pragma unroll 8
    for (int r = 0; r < 256; r++) sum += p[r * 256];
    g_g1[s * 256 + c] = sum * INV256;
}

// ---------------------------------------------------------------------------
// K1b: g2[s][j][p] = mean over i in spin s of h_two[i][j][p]
// vectorized float4; 2*512*128/4 = 32768 float4 outputs; grid 128 x 256
// ---------------------------------------------------------------------------
__global__ void k_g2(const float* __restrict__ h_two) {
    int t = blockIdx.x * 256 + threadIdx.x;   // 0..32767
    int s = t >> 14;                          // spin
    int jp4 = t & 16383;                      // float4 index into 512*128
    const float4* p = (const float4*)h_two + (size_t)s * 256 * 16384 + jp4;
    float4 acc = make_float4(0.f, 0.f, 0.f, 0.f);
#pragma unroll 8
    for (int i = 0; i < 256; i++) {
        float4 v = p[(size_t)i * 16384];
        acc.x += v.x; acc.y += v.y; acc.z += v.z; acc.w += v.w;
    }
    acc.x *= INV256; acc.y *= INV256; acc.z *= INV256; acc.w *= INV256;
    ((float4*)g_g2)[t] = acc;
}

// ---------------------------------------------------------------------------
// K2: h_one path. 128 blocks x 256 threads, 4 rows per block.
// one_in[n] = [h_one[n,0:256] | g2_up[n,0:128] | g2_dn[n,0:128]]  (512)
// h_one_new = act((one_in@W1 + b1 + global_in@Wg)/sqrt2); out=(h_one+new)/sqrt2
// global term computed redundantly per block (deterministic, cheap).
// ---------------------------------------------------------------------------
__global__ void k_one(const float* __restrict__ h_one,
                      const float* __restrict__ W1,
                      const float* __restrict__ b1,
                      const float* __restrict__ Wg,
                      float* __restrict__ out_one) {
    __shared__ float s_in[4][512];
    __shared__ float s_g1[512];
    int tid = threadIdx.x;
    int r0 = blockIdx.x * 4;

    // stage one_in rows + g1 into shared
#pragma unroll
    for (int it = 0; it < 8; it++) {
        int idx = tid + it * 256;          // 0..2047
        int rr = idx >> 9;
        int k  = idx & 511;
        int n  = r0 + rr;
        float v;
        if (k < 256)      v = h_one[n * 256 + k];
        else if (k < 384) v = g_g2[0 * 65536 + n * 128 + (k - 256)];
        else              v = g_g2[1 * 65536 + n * 128 + (k - 384)];
        s_in[rr][k] = v;
    }
    s_g1[tid] = g_g1[tid];
    s_g1[tid + 256] = g_g1[tid + 256];
    __syncthreads();

    int c = tid;
    float a0 = 0.f, a1 = 0.f, a2 = 0.f, a3 = 0.f;
    float ag = b1[c];
#pragma unroll 8
    for (int k = 0; k < 512; k++) {
        float w = W1[k * 256 + c];
        a0 += s_in[0][k] * w;
        a1 += s_in[1][k] * w;
        a2 += s_in[2][k] * w;
        a3 += s_in[3][k] * w;
        ag += s_g1[k] * Wg[k * 256 + c];
    }
    float acc[4] = {a0, a1, a2, a3};
#pragma unroll
    for (int rr = 0; rr < 4; rr++) {
        float pre = (acc[rr] + ag) * RSQRT2;
        float val = (s_in[rr][c] + GAIN * tanhf(pre)) * RSQRT2;
        out_one[(r0 + rr) * 256 + c] = val;
    }
}

// ---------------------------------------------------------------------------
// K3: main h_two kernel. C = (A + gain*tanh(A@W2 + b2)) / sqrt2
// A = h_two viewed as (262144,128). Tile: 64 rows x 128 cols per block,
// 256 threads, each thread 8 rows x 4 cols. W2 (64KB) + A tile (32KB) in smem.
// ---------------------------------------------------------------------------
__global__ void __launch_bounds__(256, 2)
k_two(const float* __restrict__ h_two,
      const float* __restrict__ W2,
      const float* __restrict__ b2,
      float* __restrict__ out_two) {
    extern __shared__ float smem[];
    float* Bs = smem;                // 128*128 floats
    float* As = smem + 128 * 128;    // 64*128 floats
    float4* Bs4 = (float4*)Bs;
    float4* As4 = (float4*)As;

    int tid = threadIdx.x;
    int rowBase = blockIdx.x * 64;

    // load W2 (4096 float4) and A tile (2048 float4)
    const float4* W24 = (const float4*)W2;
#pragma unroll
    for (int i = 0; i < 16; i++) Bs4[tid + i * 256] = W24[tid + i * 256];
    const float4* A4 = (const float4*)h_two + (size_t)rowBase * 32;
#pragma unroll
    for (int i = 0; i < 8; i++) As4[tid + i * 256] = A4[tid + i * 256];
    __syncthreads();

    int tx = tid & 31;    // column group: cols tx*4 .. tx*4+3
    int ty = tid >> 5;    // row group: rows ty*8 .. ty*8+7

    float acc[8][4];
#pragma unroll
    for (int r = 0; r < 8; r++)
#pragma unroll
        for (int q = 0; q < 4; q++) acc[r][q] = 0.f;

    const float* a_ptr = As + (ty * 8) * 128;

#pragma unroll 16
    for (int k = 0; k < 128; k++) {
        float4 b = Bs4[k * 32 + tx];
#pragma unroll
        for (int r = 0; r < 8; r++) {
            float a = a_ptr[r * 128 + k];
            acc[r][0] += a * b.x;
            acc[r][1] += a * b.y;
            acc[r][2] += a * b.z;
            acc[r][3] += a * b.w;
        }
    }

    float4 bb = ((const float4*)b2)[tx];
    float4* out4 = (float4*)out_two + (size_t)rowBase * 32 + tx;
#pragma unroll
    for (int r = 0; r < 8; r++) {
        int row = ty * 8 + r;
        float4 ao = As4[row * 32 + tx];
        float4 o;
        o.x = (ao.x + GAIN * tanhf(acc[r][0] + bb.x)) * RSQRT2;
        o.y = (ao.y + GAIN * tanhf(acc[r][1] + bb.y)) * RSQRT2;
        o.z = (ao.z + GAIN * tanhf(acc[r][2] + bb.z)) * RSQRT2;
        o.w = (ao.w + GAIN * tanhf(acc[r][3] + bb.w)) * RSQRT2;
        out4[(size_t)row * 32] = o;
    }
}

// ---------------------------------------------------------------------------
extern "C" void kernel_launch(void* const* d_in, const int* in_sizes, int n_in,
                              void* d_out, int out_size) {
    const float* h_one = (const float*)d_in[0];
    const float* h_two = (const float*)d_in[1];
    const float* W1    = (const float*)d_in[2];
    const float* b1    = (const float*)d_in[3];
    const float* Wg    = (const float*)d_in[4];
    const float* W2    = (const float*)d_in[5];
    const float* b2    = (const float*)d_in[6];

    float* out_one = (float*)d_out;
    float* out_two = (float*)d_out + 512 * 256;

    cudaFuncSetAttribute(k_two, cudaFuncAttributeMaxDynamicSharedMemorySize,
                         (128 * 128 + 64 * 128) * sizeof(float));

    k_g1<<<2, 256>>>(h_one);
    k_g2<<<128, 256>>>(h_two);
    k_one<<<128, 256>>>(h_one, W1, b1, Wg, out_one);
    k_two<<<4096, 256, (128 * 128 + 64 * 128) * sizeof(float)>>>(h_two, W2, b2, out_two);
}

// round 2
// speedup vs baseline: 1.0462x; 1.0462x over previous
#include <cuda_runtime.h>

// ---------------------------------------------------------------------------
// FermiLayer: N=512 (256 up / 256 dn), SINGLE=256, PAIR=128
// inputs: [0] h_one (512,256) [1] h_two (512,512,128) [2] W1 (512,256)
//         [3] b1 (256) [4] Wg (512,256) [5] W2 (128,128) [6] b2 (128)
// output: [h_one_out (512*256) | h_two_out (512*512*128)] fp32
// ---------------------------------------------------------------------------

#define GAIN    1.5927812698663017f
#define RSQRT2  0.7071067811865475f
#define INV256  0.00390625f

typedef unsigned long long u64;

// scratch (allocation-free rule: __device__ globals)
__device__ float g_g2[2 * 512 * 128];       // per-spin mean over senders
__device__ float g_g2p[4 * 2 * 512 * 128];  // partial sums (4 i-chunks)
__device__ float g_g1[512];                 // [g1_up(256) | g1_dn(256)]

// HW tanh (max abs err ~5e-4, RMS ~1e-4; threshold is 1e-3)
__device__ __forceinline__ float tanh_fast(float x) {
    float y;
    asm("tanh.approx.f32 %0, %1;" : "=f"(y) : "f"(x));
    return y;
}
__device__ __forceinline__ u64 dup2(float a) {
    u64 r;
    asm("mov.b64 %0, {%1, %1};" : "=l"(r) : "f"(a));
    return r;
}
__device__ __forceinline__ void fma2(u64& d, u64 a, u64 b) {
    asm("fma.rn.f32x2 %0, %1, %2, %0;" : "+l"(d) : "l"(a), "l"(b));
}
__device__ __forceinline__ float2 unpk(u64 v) {
    float2 f;
    asm("mov.b64 {%0, %1}, %2;" : "=f"(f.x), "=f"(f.y) : "l"(v));
    return f;
}
__device__ __forceinline__ u64 pk(float lo, float hi) {
    u64 r;
    asm("mov.b64 %0, {%1, %2};" : "=l"(r) : "f"(lo), "f"(hi));
    return r;
}

// ---------------------------------------------------------------------------
// K1a: g1[s*256+c] = mean over 256 rows of h_one for spin s
// ---------------------------------------------------------------------------
__global__ void k_g1(const float* __restrict__ h_one) {
    int s = blockIdx.x;
    int c = threadIdx.x;
    const float* p = h_one + (size_t)s * 256 * 256 + c;
    float sum = 0.f;
#pragma unroll 8
    for (int r = 0; r < 256; r++) sum += p[r * 256];
    g_g1[s * 256 + c] = sum * INV256;
}

// ---------------------------------------------------------------------------
// K1b-part: partial sums of h_two over i in 64-sender chunks. 512 blocks.
// ---------------------------------------------------------------------------
__global__ void k_g2p(const float* __restrict__ h_two) {
    int q = blockIdx.x >> 7;                       // i-chunk 0..3
    int t = (blockIdx.x & 127) * 256 + threadIdx.x; // 0..32767
    int s = t >> 14;                               // spin
    int jp4 = t & 16383;
    const float4* p = (const float4*)h_two + (size_t)(s * 256 + q * 64) * 16384 + jp4;
    float4 acc = make_float4(0.f, 0.f, 0.f, 0.f);
#pragma unroll 8
    for (int i = 0; i < 64; i++) {
        float4 v = p[(size_t)i * 16384];
        acc.x += v.x; acc.y += v.y; acc.z += v.z; acc.w += v.w;
    }
    ((float4*)g_g2p)[q * 32768 + t] = acc;
}

// K1b-combine: g2 = (sum of 4 partials) / 256
__global__ void k_g2c() {
    int t = blockIdx.x * 256 + threadIdx.x;        // 0..32767
    const float4* p = (const float4*)g_g2p;
    float4 a = p[t], b = p[32768 + t], c = p[65536 + t], d = p[98304 + t];
    float4 o;
    o.x = (a.x + b.x + c.x + d.x) * INV256;
    o.y = (a.y + b.y + c.y + d.y) * INV256;
    o.z = (a.z + b.z + c.z + d.z) * INV256;
    o.w = (a.w + b.w + c.w + d.w) * INV256;
    ((float4*)g_g2)[t] = o;
}

// ---------------------------------------------------------------------------
// K2: h_one path (128 blocks x 256 threads, 4 rows/block)
// ---------------------------------------------------------------------------
__global__ void k_one(const float* __restrict__ h_one,
                      const float* __restrict__ W1,
                      const float* __restrict__ b1,
                      const float* __restrict__ Wg,
                      float* __restrict__ out_one) {
    __shared__ float s_in[4][512];
    __shared__ float s_g1[512];
    int tid = threadIdx.x;
    int r0 = blockIdx.x * 4;

#pragma unroll
    for (int it = 0; it < 8; it++) {
        int idx = tid + it * 256;
        int rr = idx >> 9;
        int k  = idx & 511;
        int n  = r0 + rr;
        float v;
        if (k < 256)      v = h_one[n * 256 + k];
        else if (k < 384) v = g_g2[n * 128 + (k - 256)];
        else              v = g_g2[65536 + n * 128 + (k - 384)];
        s_in[rr][k] = v;
    }
    s_g1[tid] = g_g1[tid];
    s_g1[tid + 256] = g_g1[tid + 256];
    __syncthreads();

    int c = tid;
    float a0 = 0.f, a1 = 0.f, a2 = 0.f, a3 = 0.f;
    float ag = b1[c];
#pragma unroll 8
    for (int k = 0; k < 512; k++) {
        float w = W1[k * 256 + c];
        a0 += s_in[0][k] * w;
        a1 += s_in[1][k] * w;
        a2 += s_in[2][k] * w;
        a3 += s_in[3][k] * w;
        ag += s_g1[k] * Wg[k * 256 + c];
    }
    float acc[4] = {a0, a1, a2, a3};
#pragma unroll
    for (int rr = 0; rr < 4; rr++) {
        float pre = (acc[rr] + ag) * RSQRT2;
        out_one[(r0 + rr) * 256 + c] = (s_in[rr][c] + GAIN * tanh_fast(pre)) * RSQRT2;
    }
}

// ---------------------------------------------------------------------------
// K3: main h_two kernel using packed fma.rn.f32x2.
// C = (A + gain*tanh(A@W2 + b2)) / sqrt2, A = h_two as (262144,128).
// Tile 64 rows x 128 cols, 256 threads; thread = 4 rows x 8 cols
// (col groups tx*4 and 64+tx*4). Accumulators are f32x2 pairs seeded w/ bias.
// ---------------------------------------------------------------------------
__global__ void __launch_bounds__(256, 2)
k_two(const float* __restrict__ h_two,
      const float* __restrict__ W2,
      const float* __restrict__ b2,
      float* __restrict__ out_two) {
    extern __shared__ float smem[];
    float* Bs = smem;                // 128*128
    float* As = smem + 128 * 128;    // 64*128
    float4* Bs4 = (float4*)Bs;
    float4* As4 = (float4*)As;

    int tid = threadIdx.x;
    int rowBase = blockIdx.x * 64;
    int tx = tid & 15;       // col group
    int ty = tid >> 4;       // row group (4 rows)

    // stage W2 (4096 f4) + A tile (2048 f4)
    const float4* W24 = (const float4*)W2;
#pragma unroll
    for (int i = 0; i < 16; i++) Bs4[tid + i * 256] = W24[tid + i * 256];
    const float4* A4 = (const float4*)h_two + (size_t)rowBase * 32;
#pragma unroll
    for (int i = 0; i < 8; i++) As4[tid + i * 256] = A4[tid + i * 256];
    __syncthreads();

    // acc[r][p]: r = row 0..3, p = pair 0..3 (cols tx*4+{0,1},{2,3}, 64+tx*4+{0,1},{2,3})
    float4 bb0 = ((const float4*)b2)[tx];
    float4 bb1 = ((const float4*)b2)[16 + tx];
    u64 bias[4] = { pk(bb0.x, bb0.y), pk(bb0.z, bb0.w),
                    pk(bb1.x, bb1.y), pk(bb1.z, bb1.w) };
    u64 acc[4][4];
#pragma unroll
    for (int r = 0; r < 4; r++)
#pragma unroll
        for (int p = 0; p < 4; p++) acc[r][p] = bias[p];

    const float* a_base = As + (ty * 4) * 128;

#pragma unroll 8
    for (int k = 0; k < 128; k++) {
        // b row k: 8 cols as 4 packed pairs (2x LDS.128, contiguous across tx)
        ulonglong2 b01 = *(const ulonglong2*)(Bs + k * 128 + tx * 4);
        ulonglong2 b23 = *(const ulonglong2*)(Bs + k * 128 + 64 + tx * 4);
#pragma unroll
        for (int r = 0; r < 4; r++) {
            u64 a = dup2(a_base[r * 128 + k]);
            fma2(acc[r][0], a, b01.x);
            fma2(acc[r][1], a, b01.y);
            fma2(acc[r][2], a, b23.x);
            fma2(acc[r][3], a, b23.y);
        }
    }

    float4* out4 = (float4*)out_two + (size_t)rowBase * 32;
#pragma unroll
    for (int r = 0; r < 4; r++) {
        int row = ty * 4 + r;
        float2 p0 = unpk(acc[r][0]), p1 = unpk(acc[r][1]);
        float2 p2 = unpk(acc[r][2]), p3 = unpk(acc[r][3]);
        float4 ao0 = As4[row * 32 + tx];
        float4 ao1 = As4[row * 32 + 16 + tx];
        float4 o0, o1;
        o0.x = (ao0.x + GAIN * tanh_fast(p0.x)) * RSQRT2;
        o0.y = (ao0.y + GAIN * tanh_fast(p0.y)) * RSQRT2;
        o0.z = (ao0.z + GAIN * tanh_fast(p1.x)) * RSQRT2;
        o0.w = (ao0.w + GAIN * tanh_fast(p1.y)) * RSQRT2;
        o1.x = (ao1.x + GAIN * tanh_fast(p2.x)) * RSQRT2;
        o1.y = (ao1.y + GAIN * tanh_fast(p2.y)) * RSQRT2;
        o1.z = (ao1.z + GAIN * tanh_fast(p3.x)) * RSQRT2;
        o1.w = (ao1.w + GAIN * tanh_fast(p3.y)) * RSQRT2;
        out4[(size_t)row * 32 + tx] = o0;
        out4[(size_t)row * 32 + 16 + tx] = o1;
    }
}

// ---------------------------------------------------------------------------
extern "C" void kernel_launch(void* const* d_in, const int* in_sizes, int n_in,
                              void* d_out, int out_size) {
    const float* h_one = (const float*)d_in[0];
    const float* h_two = (const float*)d_in[1];
    const float* W1    = (const float*)d_in[2];
    const float* b1    = (const float*)d_in[3];
    const float* Wg    = (const float*)d_in[4];
    const float* W2    = (const float*)d_in[5];
    const float* b2    = (const float*)d_in[6];

    float* out_one = (float*)d_out;
    float* out_two = (float*)d_out + 512 * 256;

    int smem_two = (128 * 128 + 64 * 128) * sizeof(float);
    cudaFuncSetAttribute(k_two, cudaFuncAttributeMaxDynamicSharedMemorySize, smem_two);

    k_g1<<<2, 256>>>(h_one);
    k_g2p<<<512, 256>>>(h_two);
    k_g2c<<<128, 256>>>();
    k_one<<<128, 256>>>(h_one, W1, b1, Wg, out_one);
    k_two<<<4096, 256, smem_two>>>(h_two, W2, b2, out_two);
}

// round 3
// speedup vs baseline: 1.1689x; 1.1174x over previous
#include <cuda_runtime.h>

// ---------------------------------------------------------------------------
// FermiLayer: N=512 (256 up / 256 dn), SINGLE=256, PAIR=128
// inputs: [0] h_one (512,256) [1] h_two (512,512,128) [2] W1 (512,256)
//         [3] b1 (256) [4] Wg (512,256) [5] W2 (128,128) [6] b2 (128)
// output: [h_one_out (512*256) | h_two_out (512*512*128)] fp32
// ---------------------------------------------------------------------------

#define GAIN    1.5927812698663017f
#define RSQRT2  0.7071067811865475f
#define INV256  0.00390625f

typedef unsigned long long u64;

// scratch (allocation-free rule: __device__ globals)
__device__ float g_g2[2 * 512 * 128];       // per-spin mean over senders
__device__ float g_g2p[4 * 2 * 512 * 128];  // partial sums (4 i-chunks)
__device__ float g_g1[512];                 // [g1_up(256) | g1_dn(256)]
__device__ float g_gt[256];                 // b1 + global_in @ Wg

__device__ __forceinline__ float tanh_fast(float x) {
    float y;
    asm("tanh.approx.f32 %0, %1;" : "=f"(y) : "f"(x));
    return y;
}
__device__ __forceinline__ u64 dup2(float a) {
    u64 r;
    asm("mov.b64 %0, {%1, %1};" : "=l"(r) : "f"(a));
    return r;
}
__device__ __forceinline__ void fma2(u64& d, u64 a, u64 b) {
    asm("fma.rn.f32x2 %0, %1, %2, %0;" : "+l"(d) : "l"(a), "l"(b));
}
__device__ __forceinline__ float2 unpk(u64 v) {
    float2 f;
    asm("mov.b64 {%0, %1}, %2;" : "=f"(f.x), "=f"(f.y) : "l"(v));
    return f;
}
__device__ __forceinline__ u64 pk(float lo, float hi) {
    u64 r;
    asm("mov.b64 %0, {%1, %2};" : "=l"(r) : "f"(lo), "f"(hi));
    return r;
}

// ---------------------------------------------------------------------------
// K1a: g1[s*256+c] = mean over 256 rows of h_one for spin s
// ---------------------------------------------------------------------------
__global__ void k_g1(const float* __restrict__ h_one) {
    int s = blockIdx.x;
    int c = threadIdx.x;
    const float* p = h_one + (size_t)s * 256 * 256 + c;
    float sum = 0.f;
#pragma unroll 8
    for (int r = 0; r < 256; r++) sum += p[r * 256];
    g_g1[s * 256 + c] = sum * INV256;
}

// ---------------------------------------------------------------------------
// K1a': gt[c] = b1[c] + sum_k g1[k] * Wg[k,c]   (1 block, 256 threads)
// ---------------------------------------------------------------------------
__global__ void k_gt(const float* __restrict__ Wg, const float* __restrict__ b1) {
    __shared__ float s_g1[512];
    int c = threadIdx.x;
    s_g1[c] = g_g1[c];
    s_g1[c + 256] = g_g1[c + 256];
    __syncthreads();
    float acc = b1[c];
#pragma unroll 4
    for (int kb = 0; kb < 64; kb++) {
        float w[8];
#pragma unroll
        for (int i = 0; i < 8; i++) w[i] = Wg[(kb * 8 + i) * 256 + c];
#pragma unroll
        for (int i = 0; i < 8; i++) acc += s_g1[kb * 8 + i] * w[i];
    }
    g_gt[c] = acc;
}

// ---------------------------------------------------------------------------
// K1b-part: partial sums of h_two over i in 64-sender chunks. 512 blocks.
// ---------------------------------------------------------------------------
__global__ void k_g2p(const float* __restrict__ h_two) {
    int q = blockIdx.x >> 7;
    int t = (blockIdx.x & 127) * 256 + threadIdx.x;
    int s = t >> 14;
    int jp4 = t & 16383;
    const float4* p = (const float4*)h_two + (size_t)(s * 256 + q * 64) * 16384 + jp4;
    float4 acc = make_float4(0.f, 0.f, 0.f, 0.f);
#pragma unroll 8
    for (int i = 0; i < 64; i++) {
        float4 v = p[(size_t)i * 16384];
        acc.x += v.x; acc.y += v.y; acc.z += v.z; acc.w += v.w;
    }
    ((float4*)g_g2p)[q * 32768 + t] = acc;
}

__global__ void k_g2c() {
    int t = blockIdx.x * 256 + threadIdx.x;
    const float4* p = (const float4*)g_g2p;
    float4 a = p[t], b = p[32768 + t], c = p[65536 + t], d = p[98304 + t];
    float4 o;
    o.x = (a.x + b.x + c.x + d.x) * INV256;
    o.y = (a.y + b.y + c.y + d.y) * INV256;
    o.z = (a.z + b.z + c.z + d.z) * INV256;
    o.w = (a.w + b.w + c.w + d.w) * INV256;
    ((float4*)g_g2)[t] = o;
}

// ---------------------------------------------------------------------------
// K2: h_one path. 256 blocks x 256 threads, 2 rows/block.
// Interleaved smem rows (LDS.64 broadcast) + 8-deep W1 prefetch for MLP.
// ---------------------------------------------------------------------------
__global__ void __launch_bounds__(256)
k_one(const float* __restrict__ h_one,
      const float* __restrict__ W1,
      float* __restrict__ out_one) {
    __shared__ float s_in[1024];   // [k][r] interleaved, k=0..511, r=0..1
    int tid = threadIdx.x;
    int r0 = blockIdx.x * 2;

#pragma unroll
    for (int i = 0; i < 4; i++) {
        int e = tid + i * 256;     // 0..1023
        int k = e >> 1;
        int r = e & 1;
        int n = r0 + r;
        float v;
        if (k < 256)      v = h_one[n * 256 + k];
        else if (k < 384) v = g_g2[n * 128 + (k - 256)];
        else              v = g_g2[65536 + n * 128 + (k - 384)];
        s_in[k * 2 + r] = v;
    }
    __syncthreads();

    const float2* s2 = (const float2*)s_in;
    int c = tid;
    float acc0 = 0.f, acc1 = 0.f;
#pragma unroll 4
    for (int kb = 0; kb < 64; kb++) {
        float w[8];
#pragma unroll
        for (int i = 0; i < 8; i++) w[i] = W1[(kb * 8 + i) * 256 + c];
#pragma unroll
        for (int i = 0; i < 8; i++) {
            float2 a = s2[kb * 8 + i];
            acc0 += a.x * w[i];
            acc1 += a.y * w[i];
        }
    }
    float gt = g_gt[c];
    float pre0 = (acc0 + gt) * RSQRT2;
    float pre1 = (acc1 + gt) * RSQRT2;
    out_one[r0 * 256 + c]       = (s_in[c * 2]     + GAIN * tanh_fast(pre0)) * RSQRT2;
    out_one[(r0 + 1) * 256 + c] = (s_in[c * 2 + 1] + GAIN * tanh_fast(pre1)) * RSQRT2;
}

// ---------------------------------------------------------------------------
// K3: h_two kernel. C = (A + gain*tanh(A@W2 + b2)) / sqrt2.
// Tile 128 rows x 128 cols, 256 threads; thread = 8 rows x 8 cols.
// A rows padded (stride 132 floats) to dodge LDS.64 bank conflicts.
// k processed in pairs: A via LDS.64, B via 4x LDS.128, FMA via fma.rn.f32x2.
// ---------------------------------------------------------------------------
#define A_STRIDE 132

__global__ void __launch_bounds__(256, 1)
k_two(const float* __restrict__ h_two,
      const float* __restrict__ W2,
      const float* __restrict__ b2,
      float* __restrict__ out_two) {
    extern __shared__ float smem[];
    float* Bs = smem;                    // [k][col] 128*128
    float* As = smem + 128 * 128;        // [row][k] 128 x A_STRIDE

    int tid = threadIdx.x;
    int rowBase = blockIdx.x * 128;
    int cx = tid & 15;     // col group: cols cx*8 .. cx*8+7
    int ry = tid >> 4;     // row group: rows ry*8 .. ry*8+7

    // stage W2 (4096 f4, direct layout) and A (4096 f4, padded rows)
    const float4* W24 = (const float4*)W2;
    float4* Bs4 = (float4*)Bs;
#pragma unroll
    for (int i = 0; i < 16; i++) Bs4[tid + i * 256] = W24[tid + i * 256];
    const float4* A4 = (const float4*)h_two + (size_t)rowBase * 32;
#pragma unroll
    for (int i = 0; i < 16; i++) {
        int idx = tid + i * 256;       // 0..4095
        int row = idx >> 5;
        int kc  = idx & 31;
        float4 v = A4[idx];
        *(float4*)(As + row * A_STRIDE + kc * 4) = v;
    }
    __syncthreads();

    // acc[r][p]: pairs of cols (cx*8+2p, cx*8+2p+1), seeded with bias
    float4 u = ((const float4*)b2)[cx * 2];
    float4 v = ((const float4*)b2)[cx * 2 + 1];
    u64 bias[4] = { pk(u.x, u.y), pk(u.z, u.w), pk(v.x, v.y), pk(v.z, v.w) };
    u64 acc[8][4];
#pragma unroll
    for (int r = 0; r < 8; r++)
#pragma unroll
        for (int p = 0; p < 4; p++) acc[r][p] = bias[p];

    const float* a_base = As + (ry * 8) * A_STRIDE;

#pragma unroll 4
    for (int k = 0; k < 128; k += 2) {
        // B rows k and k+1, 8 cols each, as packed pairs
        const ulonglong2* bp0 = (const ulonglong2*)(Bs + k * 128 + cx * 8);
        const ulonglong2* bp1 = (const ulonglong2*)(Bs + (k + 1) * 128 + cx * 8);
        ulonglong2 b0a = bp0[0], b0b = bp0[1];
        ulonglong2 b1a = bp1[0], b1b = bp1[1];
#pragma unroll
        for (int r = 0; r < 8; r++) {
            float2 a = *(const float2*)(a_base + r * A_STRIDE + k);
            u64 a0 = dup2(a.x);
            u64 a1 = dup2(a.y);
            fma2(acc[r][0], a0, b0a.x);
            fma2(acc[r][1], a0, b0a.y);
            fma2(acc[r][2], a0, b0b.x);
            fma2(acc[r][3], a0, b0b.y);
            fma2(acc[r][0], a1, b1a.x);
            fma2(acc[r][1], a1, b1a.y);
            fma2(acc[r][2], a1, b1b.x);
            fma2(acc[r][3], a1, b1b.y);
        }
    }

    float4* out4 = (float4*)out_two + (size_t)rowBase * 32;
#pragma unroll
    for (int r = 0; r < 8; r++) {
        int row = ry * 8 + r;
        const float* arow = As + row * A_STRIDE + cx * 8;
        float4 o0, o1;
        float2 q0 = unpk(acc[r][0]), q1 = unpk(acc[r][1]);
        float2 q2 = unpk(acc[r][2]), q3 = unpk(acc[r][3]);
        o0.x = (arow[0] + GAIN * tanh_fast(q0.x)) * RSQRT2;
        o0.y = (arow[1] + GAIN * tanh_fast(q0.y)) * RSQRT2;
        o0.z = (arow[2] + GAIN * tanh_fast(q1.x)) * RSQRT2;
        o0.w = (arow[3] + GAIN * tanh_fast(q1.y)) * RSQRT2;
        o1.x = (arow[4] + GAIN * tanh_fast(q2.x)) * RSQRT2;
        o1.y = (arow[5] + GAIN * tanh_fast(q2.y)) * RSQRT2;
        o1.z = (arow[6] + GAIN * tanh_fast(q3.x)) * RSQRT2;
        o1.w = (arow[7] + GAIN * tanh_fast(q3.y)) * RSQRT2;
        out4[(size_t)row * 32 + cx * 2]     = o0;
        out4[(size_t)row * 32 + cx * 2 + 1] = o1;
    }
}

// ---------------------------------------------------------------------------
extern "C" void kernel_launch(void* const* d_in, const int* in_sizes, int n_in,
                              void* d_out, int out_size) {
    const float* h_one = (const float*)d_in[0];
    const float* h_two = (const float*)d_in[1];
    const float* W1    = (const float*)d_in[2];
    const float* b1    = (const float*)d_in[3];
    const float* Wg    = (const float*)d_in[4];
    const float* W2    = (const float*)d_in[5];
    const float* b2    = (const float*)d_in[6];

    float* out_one = (float*)d_out;
    float* out_two = (float*)d_out + 512 * 256;

    int smem_two = (128 * 128 + 128 * A_STRIDE) * sizeof(float);
    cudaFuncSetAttribute(k_two, cudaFuncAttributeMaxDynamicSharedMemorySize, smem_two);

    k_g1<<<2, 256>>>(h_one);
    k_gt<<<1, 256>>>(Wg, b1);
    k_g2p<<<512, 256>>>(h_two);
    k_g2c<<<128, 256>>>();
    k_one<<<256, 256>>>(h_one, W1, out_one);
    k_two<<<2048, 256, smem_two>>>(h_two, W2, b2, out_two);
}

// round 5
// speedup vs baseline: 1.3873x; 1.1868x over previous
#include <cuda_runtime.h>
#include <cuda_bf16.h>
#include <cstdint>

// ---------------------------------------------------------------------------
// FermiLayer: N=512 (256 up / 256 dn), SINGLE=256, PAIR=128
// inputs: [0] h_one (512,256) [1] h_two (512,512,128) [2] W1 (512,256)
//         [3] b1 (256) [4] Wg (512,256) [5] W2 (128,128) [6] b2 (128)
// output: [h_one_out | h_two_out] fp32
// k_two: warp-level bf16 mma.sync (HMMA) with 3-term double-split for
// fp32-class accuracy (tcgen05 is not available: harness PTX target=sm_103).
// ---------------------------------------------------------------------------

#define GAIN    1.5927812698663017f
#define RSQRT2  0.7071067811865475f
#define INV256  0.00390625f

typedef unsigned long long u64;
typedef unsigned int u32;

// scratch (__device__ globals: allocation-free rule)
__device__ float g_g2[2 * 512 * 128];
__device__ float g_g2p[4 * 2 * 512 * 128];
__device__ float g_g1[512];
__device__ float g_gt[256];
// W2^T bf16 hi/lo in padded [n][k] layout (row stride 272B), ready for smem copy
__device__ __align__(16) unsigned char g_w2hi[35840];
__device__ __align__(16) unsigned char g_w2lo[35840];

__device__ __forceinline__ float tanh_fast(float x) {
    float y;
    asm("tanh.approx.f32 %0, %1;" : "=f"(y) : "f"(x));
    return y;
}
__device__ __forceinline__ u32 smem_u32(const void* p) {
    u32 a;
    asm("{ .reg .u64 t; cvta.to.shared.u64 t, %1; cvt.u32.u64 %0, t; }" : "=r"(a) : "l"(p));
    return a;
}
__device__ __forceinline__ void ldsm4(u32* r, u32 addr) {
    asm volatile("ldmatrix.sync.aligned.m8n8.x4.shared.b16 {%0,%1,%2,%3}, [%4];"
                 : "=r"(r[0]), "=r"(r[1]), "=r"(r[2]), "=r"(r[3]) : "r"(addr));
}
__device__ __forceinline__ void mma16816(float* c, const u32* a, const u32* b) {
    asm volatile(
        "mma.sync.aligned.m16n8k16.row.col.f32.bf16.bf16.f32 "
        "{%0,%1,%2,%3}, {%4,%5,%6,%7}, {%8,%9}, {%0,%1,%2,%3};"
        : "+f"(c[0]), "+f"(c[1]), "+f"(c[2]), "+f"(c[3])
        : "r"(a[0]), "r"(a[1]), "r"(a[2]), "r"(a[3]), "r"(b[0]), "r"(b[1]));
}
__device__ __forceinline__ void split_pack(const float* f, u64& hp, u64& lp) {
    hp = 0; lp = 0;
#pragma unroll
    for (int j = 0; j < 4; j++) {
        __nv_bfloat16 h = __float2bfloat16(f[j]);
        __nv_bfloat16 l = __float2bfloat16(f[j] - __bfloat162float(h));
        hp |= (u64)__bfloat16_as_ushort(h) << (16 * j);
        lp |= (u64)__bfloat16_as_ushort(l) << (16 * j);
    }
}

// ---------------------------------------------------------------------------
__global__ void k_g1(const float* __restrict__ h_one) {
    int s = blockIdx.x, c = threadIdx.x;
    const float* p = h_one + (size_t)s * 65536 + c;
    float sum = 0.f;
#pragma unroll 8
    for (int r = 0; r < 256; r++) sum += p[r * 256];
    g_g1[s * 256 + c] = sum * INV256;
}

__global__ void k_gt(const float* __restrict__ Wg, const float* __restrict__ b1) {
    __shared__ float s_g1[512];
    int c = threadIdx.x;
    s_g1[c] = g_g1[c];
    s_g1[c + 256] = g_g1[c + 256];
    __syncthreads();
    float acc = b1[c];
#pragma unroll 4
    for (int kb = 0; kb < 64; kb++) {
        float w[8];
#pragma unroll
        for (int i = 0; i < 8; i++) w[i] = Wg[(kb * 8 + i) * 256 + c];
#pragma unroll
        for (int i = 0; i < 8; i++) acc += s_g1[kb * 8 + i] * w[i];
    }
    g_gt[c] = acc;
}

__global__ void k_g2p(const float* __restrict__ h_two) {
    int q = blockIdx.x >> 7;
    int t = (blockIdx.x & 127) * 256 + threadIdx.x;
    int s = t >> 14;
    int jp4 = t & 16383;
    const float4* p = (const float4*)h_two + (size_t)(s * 256 + q * 64) * 16384 + jp4;
    float4 acc = make_float4(0.f, 0.f, 0.f, 0.f);
#pragma unroll 8
    for (int i = 0; i < 64; i++) {
        float4 v = p[(size_t)i * 16384];
        acc.x += v.x; acc.y += v.y; acc.z += v.z; acc.w += v.w;
    }
    ((float4*)g_g2p)[q * 32768 + t] = acc;
}

__global__ void k_g2c() {
    int t = blockIdx.x * 256 + threadIdx.x;
    const float4* p = (const float4*)g_g2p;
    float4 a = p[t], b = p[32768 + t], c = p[65536 + t], d = p[98304 + t];
    float4 o;
    o.x = (a.x + b.x + c.x + d.x) * INV256;
    o.y = (a.y + b.y + c.y + d.y) * INV256;
    o.z = (a.z + b.z + c.z + d.z) * INV256;
    o.w = (a.w + b.w + c.w + d.w) * INV256;
    ((float4*)g_g2)[t] = o;
}

// ---------------------------------------------------------------------------
// K2: h_one path (256 blocks x 256 threads, 2 rows/block)
// ---------------------------------------------------------------------------
__global__ void __launch_bounds__(256)
k_one(const float* __restrict__ h_one,
      const float* __restrict__ W1,
      float* __restrict__ out_one) {
    __shared__ float s_in[1024];
    int tid = threadIdx.x;
    int r0 = blockIdx.x * 2;
#pragma unroll
    for (int i = 0; i < 4; i++) {
        int e = tid + i * 256;
        int k = e >> 1;
        int r = e & 1;
        int n = r0 + r;
        float v;
        if (k < 256)      v = h_one[n * 256 + k];
        else if (k < 384) v = g_g2[n * 128 + (k - 256)];
        else              v = g_g2[65536 + n * 128 + (k - 384)];
        s_in[k * 2 + r] = v;
    }
    __syncthreads();
    const float2* s2 = (const float2*)s_in;
    int c = tid;
    float acc0 = 0.f, acc1 = 0.f;
#pragma unroll 4
    for (int kb = 0; kb < 64; kb++) {
        float w[8];
#pragma unroll
        for (int i = 0; i < 8; i++) w[i] = W1[(kb * 8 + i) * 256 + c];
#pragma unroll
        for (int i = 0; i < 8; i++) {
            float2 a = s2[kb * 8 + i];
            acc0 += a.x * w[i];
            acc1 += a.y * w[i];
        }
    }
    float gt = g_gt[c];
    out_one[r0 * 256 + c]       = (s_in[c * 2]     + GAIN * tanh_fast((acc0 + gt) * RSQRT2)) * RSQRT2;
    out_one[(r0 + 1) * 256 + c] = (s_in[c * 2 + 1] + GAIN * tanh_fast((acc1 + gt) * RSQRT2)) * RSQRT2;
}

// ---------------------------------------------------------------------------
// W2 prep: W2T[n][k] = W2[k][n], split bf16 hi/lo, padded rows (272B stride).
// 16 blocks x 256 threads: t -> n = t>>5, k-quad = t&31.
// ---------------------------------------------------------------------------
#define BSTRIDE 272

__global__ void k_w2prep(const float* __restrict__ W2) {
    int t = blockIdx.x * 256 + threadIdx.x;   // 0..4095
    int n = t >> 5;
    int k = (t & 31) * 4;
    float f[4];
#pragma unroll
    for (int j = 0; j < 4; j++) f[j] = W2[(k + j) * 128 + n];
    u64 hp, lp;
    split_pack(f, hp, lp);
    *(u64*)(g_w2hi + n * BSTRIDE + k * 2) = hp;
    *(u64*)(g_w2lo + n * BSTRIDE + k * 2) = lp;
}

// ---------------------------------------------------------------------------
// K3: bf16 mma.sync h_two kernel. 4096 blocks x 256 threads.
// Tile 64x128x128; warp = m32 x n32 (warp grid 2m x 4n).
// smem: A hi/lo (64x128 bf16, stride 272B) + W hi/lo (128x128 bf16, stride 272B).
// D = Ahi*Whi + Ahi*Wlo + Alo*Whi (fp32 acc); epilogue fuses bias+tanh+residual.
// ---------------------------------------------------------------------------
#define S_AHI 0
#define S_ALO 17408
#define S_WHI 34816
#define S_WLO 69632
#define SMEM_TWO 104448

__global__ void __launch_bounds__(256, 2)
k_two(const float* __restrict__ h_two,
      const float* __restrict__ b2,
      float* __restrict__ out_two) {
    extern __shared__ char smem[];
    u32 sb = smem_u32(smem);
    int tid = threadIdx.x;
    int lane = tid & 31;
    int w = tid >> 5;
    size_t rowBase = (size_t)blockIdx.x * 64;

    // stage W2T hi/lo images (pre-padded in global): 2176 uint4 each
    {
        const uint4* wh = (const uint4*)g_w2hi;
        const uint4* wl = (const uint4*)g_w2lo;
        uint4* dh = (uint4*)(smem + S_WHI);
        uint4* dl = (uint4*)(smem + S_WLO);
        for (int idx = tid; idx < 2176; idx += 256) {
            dh[idx] = wh[idx];
            dl[idx] = wl[idx];
        }
    }
    // stage A tile: split fp32 -> bf16 hi/lo, padded rows
    {
        int rr = tid >> 5;          // 0..7
        int kc = tid & 31;          // k-quad
#pragma unroll
        for (int it = 0; it < 8; it++) {
            int row = rr + it * 8;
            float4 v = *((const float4*)(h_two + (rowBase + row) * 128) + kc);
            float f[4] = {v.x, v.y, v.z, v.w};
            u64 hp, lp;
            split_pack(f, hp, lp);
            *(u64*)(smem + S_AHI + row * BSTRIDE + kc * 8) = hp;
            *(u64*)(smem + S_ALO + row * BSTRIDE + kc * 8) = lp;
        }
    }
    __syncthreads();

    int mw = w & 1;       // m-block: rows mw*32
    int nw = w >> 1;      // n-block: cols nw*32

    // lane-static ldmatrix offsets
    u32 a_off = (u32)((mw * 32 + (lane & 15)) * BSTRIDE + ((lane >> 4) << 4));
    u32 b_off = (u32)((((lane & 7) + ((lane >> 4) << 3)) * BSTRIDE) + (((lane >> 3) & 1) << 4));

    float acc[2][4][4];   // [mi][nt][frag]
#pragma unroll
    for (int mi = 0; mi < 2; mi++)
#pragma unroll
        for (int nt = 0; nt < 4; nt++)
#pragma unroll
            for (int q = 0; q < 4; q++) acc[mi][nt][q] = 0.f;

#pragma unroll
    for (int pass = 0; pass < 3; pass++) {
        u32 Ab = sb + (pass < 2 ? S_AHI : S_ALO) + a_off;
        u32 Bb = sb + (pass == 1 ? S_WLO : S_WHI) + (u32)(nw * 32 * BSTRIDE) + b_off;
#pragma unroll
        for (int ks = 0; ks < 8; ks++) {
            u32 a0[4], a1[4], b0[4], b1[4];
            ldsm4(a0, Ab + ks * 32);
            ldsm4(a1, Ab + 16 * BSTRIDE + ks * 32);
            ldsm4(b0, Bb + ks * 32);
            ldsm4(b1, Bb + 16 * BSTRIDE + ks * 32);
            mma16816(acc[0][0], a0, b0);
            mma16816(acc[0][1], a0, b0 + 2);
            mma16816(acc[0][2], a0, b1);
            mma16816(acc[0][3], a0, b1 + 2);
            mma16816(acc[1][0], a1, b0);
            mma16816(acc[1][1], a1, b0 + 2);
            mma16816(acc[1][2], a1, b1);
            mma16816(acc[1][3], a1, b1 + 2);
        }
    }

    // epilogue: out = (A + GAIN*tanh(D + b2)) * RSQRT2
    int col0 = nw * 32 + (lane & 3) * 2;
    float2 bz[4];
#pragma unroll
    for (int nt = 0; nt < 4; nt++) bz[nt] = *(const float2*)(b2 + col0 + nt * 8);

#pragma unroll
    for (int mi = 0; mi < 2; mi++) {
        size_t r0 = rowBase + mw * 32 + mi * 16 + (lane >> 2);
#pragma unroll
        for (int half = 0; half < 2; half++) {
            size_t r = r0 + half * 8;
            const float* arow = h_two + r * 128;
            float* orow = out_two + r * 128;
#pragma unroll
            for (int nt = 0; nt < 4; nt++) {
                int c = col0 + nt * 8;
                float2 av = *(const float2*)(arow + c);
                float d0 = acc[mi][nt][half * 2 + 0] + bz[nt].x;
                float d1 = acc[mi][nt][half * 2 + 1] + bz[nt].y;
                float2 o;
                o.x = (av.x + GAIN * tanh_fast(d0)) * RSQRT2;
                o.y = (av.y + GAIN * tanh_fast(d1)) * RSQRT2;
                *(float2*)(orow + c) = o;
            }
        }
    }
}

// ---------------------------------------------------------------------------
extern "C" void kernel_launch(void* const* d_in, const int* in_sizes, int n_in,
                              void* d_out, int out_size) {
    const float* h_one = (const float*)d_in[0];
    const float* h_two = (const float*)d_in[1];
    const float* W1    = (const float*)d_in[2];
    const float* b1    = (const float*)d_in[3];
    const float* Wg    = (const float*)d_in[4];
    const float* W2    = (const float*)d_in[5];
    const float* b2    = (const float*)d_in[6];

    float* out_one = (float*)d_out;
    float* out_two = (float*)d_out + 512 * 256;

    cudaFuncSetAttribute(k_two, cudaFuncAttributeMaxDynamicSharedMemorySize, SMEM_TWO);

    k_w2prep<<<16, 256>>>(W2);
    k_g1<<<2, 256>>>(h_one);
    k_gt<<<1, 256>>>(Wg, b1);
    k_g2p<<<512, 256>>>(h_two);
    k_g2c<<<128, 256>>>();
    k_one<<<256, 256>>>(h_one, W1, out_one);
    k_two<<<4096, 256, SMEM_TWO>>>(h_two, b2, out_two);
}

// round 6
// speedup vs baseline: 1.7008x; 1.2260x over previous
#include <cuda_runtime.h>
#include <cuda_bf16.h>
#include <cstdint>

// ---------------------------------------------------------------------------
// FermiLayer: N=512 (256 up / 256 dn), SINGLE=256, PAIR=128
// inputs: [0] h_one (512,256) [1] h_two (512,512,128) [2] W1 (512,256)
//         [3] b1 (256) [4] Wg (512,256) [5] W2 (128,128) [6] b2 (128)
// output: [h_one_out | h_two_out] fp32
// k_two: bf16 mma.sync 3-term split GEMM, retiled to (64 senders x 1 receiver)
// so each CTA also emits its g2 column-sum partial (k_g2p deleted), and the
// epilogue reconstructs A from smem hi+lo (no global re-read).
// ---------------------------------------------------------------------------

#define GAIN    1.5927812698663017f
#define RSQRT2  0.7071067811865475f
#define INV256  0.00390625f

typedef unsigned long long u64;
typedef unsigned int u32;

// scratch (__device__ globals: allocation-free rule)
__device__ float g_g2[2 * 512 * 128];
__device__ float g_g2p[4 * 2 * 512 * 128];  // [q][s][j][p] partial sums (64 i each)
__device__ float g_g1[512];
__device__ float g_gt[256];
// W2^T bf16 hi/lo in padded [n][k] layout (row stride 272B)
__device__ __align__(16) unsigned char g_w2hi[35840];
__device__ __align__(16) unsigned char g_w2lo[35840];

__device__ __forceinline__ float tanh_fast(float x) {
    float y;
    asm("tanh.approx.f32 %0, %1;" : "=f"(y) : "f"(x));
    return y;
}
__device__ __forceinline__ u32 smem_u32(const void* p) {
    u32 a;
    asm("{ .reg .u64 t; cvta.to.shared.u64 t, %1; cvt.u32.u64 %0, t; }" : "=r"(a) : "l"(p));
    return a;
}
__device__ __forceinline__ void ldsm4(u32* r, u32 addr) {
    asm volatile("ldmatrix.sync.aligned.m8n8.x4.shared.b16 {%0,%1,%2,%3}, [%4];"
                 : "=r"(r[0]), "=r"(r[1]), "=r"(r[2]), "=r"(r[3]) : "r"(addr));
}
__device__ __forceinline__ void mma16816(float* c, const u32* a, const u32* b) {
    asm volatile(
        "mma.sync.aligned.m16n8k16.row.col.f32.bf16.bf16.f32 "
        "{%0,%1,%2,%3}, {%4,%5,%6,%7}, {%8,%9}, {%0,%1,%2,%3};"
        : "+f"(c[0]), "+f"(c[1]), "+f"(c[2]), "+f"(c[3])
        : "r"(a[0]), "r"(a[1]), "r"(a[2]), "r"(a[3]), "r"(b[0]), "r"(b[1]));
}
// split two floats into bf16 hi pair + bf16 lo pair (lo = exact residual, rounded)
__device__ __forceinline__ void split2(float e0, float e1, u32& hp, u32& lp) {
    asm("cvt.rn.bf16x2.f32 %0, %1, %2;" : "=r"(hp) : "f"(e1), "f"(e0));
    float h0 = __uint_as_float(hp << 16);
    float h1 = __uint_as_float(hp & 0xFFFF0000u);
    float l0 = e0 - h0, l1 = e1 - h1;
    asm("cvt.rn.bf16x2.f32 %0, %1, %2;" : "=r"(lp) : "f"(l1), "f"(l0));
}
__device__ __forceinline__ void split4(const float4& v, u64& hp, u64& lp) {
    u32 h0, l0, h1, l1;
    split2(v.x, v.y, h0, l0);
    split2(v.z, v.w, h1, l1);
    hp = (u64)h0 | ((u64)h1 << 32);
    lp = (u64)l0 | ((u64)l1 << 32);
}

// ---------------------------------------------------------------------------
__global__ void k_g1(const float* __restrict__ h_one) {
    int s = blockIdx.x, c = threadIdx.x;
    const float* p = h_one + (size_t)s * 65536 + c;
    float sum = 0.f;
#pragma unroll 8
    for (int r = 0; r < 256; r++) sum += p[r * 256];
    g_g1[s * 256 + c] = sum * INV256;
}

__global__ void k_gt(const float* __restrict__ Wg, const float* __restrict__ b1) {
    __shared__ float s_g1[512];
    int c = threadIdx.x;
    s_g1[c] = g_g1[c];
    s_g1[c + 256] = g_g1[c + 256];
    __syncthreads();
    float acc = b1[c];
#pragma unroll 4
    for (int kb = 0; kb < 64; kb++) {
        float w[8];
#pragma unroll
        for (int i = 0; i < 8; i++) w[i] = Wg[(kb * 8 + i) * 256 + c];
#pragma unroll
        for (int i = 0; i < 8; i++) acc += s_g1[kb * 8 + i] * w[i];
    }
    g_gt[c] = acc;
}

// combine 4 i-chunk partials -> g_g2 (divide by 256)
__global__ void k_g2c() {
    int t = blockIdx.x * 256 + threadIdx.x;
    const float4* p = (const float4*)g_g2p;
    float4 a = p[t], b = p[32768 + t], c = p[65536 + t], d = p[98304 + t];
    float4 o;
    o.x = (a.x + b.x + c.x + d.x) * INV256;
    o.y = (a.y + b.y + c.y + d.y) * INV256;
    o.z = (a.z + b.z + c.z + d.z) * INV256;
    o.w = (a.w + b.w + c.w + d.w) * INV256;
    ((float4*)g_g2)[t] = o;
}

// ---------------------------------------------------------------------------
// K2: h_one path (256 blocks x 256 threads, 2 rows/block)
// ---------------------------------------------------------------------------
__global__ void __launch_bounds__(256)
k_one(const float* __restrict__ h_one,
      const float* __restrict__ W1,
      float* __restrict__ out_one) {
    __shared__ float s_in[1024];
    int tid = threadIdx.x;
    int r0 = blockIdx.x * 2;
#pragma unroll
    for (int i = 0; i < 4; i++) {
        int e = tid + i * 256;
        int k = e >> 1;
        int r = e & 1;
        int n = r0 + r;
        float v;
        if (k < 256)      v = h_one[n * 256 + k];
        else if (k < 384) v = g_g2[n * 128 + (k - 256)];
        else              v = g_g2[65536 + n * 128 + (k - 384)];
        s_in[k * 2 + r] = v;
    }
    __syncthreads();
    const float2* s2 = (const float2*)s_in;
    int c = tid;
    float acc0 = 0.f, acc1 = 0.f;
#pragma unroll 4
    for (int kb = 0; kb < 64; kb++) {
        float w[8];
#pragma unroll
        for (int i = 0; i < 8; i++) w[i] = W1[(kb * 8 + i) * 256 + c];
#pragma unroll
        for (int i = 0; i < 8; i++) {
            float2 a = s2[kb * 8 + i];
            acc0 += a.x * w[i];
            acc1 += a.y * w[i];
        }
    }
    float gt = g_gt[c];
    out_one[r0 * 256 + c]       = (s_in[c * 2]     + GAIN * tanh_fast((acc0 + gt) * RSQRT2)) * RSQRT2;
    out_one[(r0 + 1) * 256 + c] = (s_in[c * 2 + 1] + GAIN * tanh_fast((acc1 + gt) * RSQRT2)) * RSQRT2;
}

// ---------------------------------------------------------------------------
// W2 prep: W2T[n][k] = W2[k][n], split bf16 hi/lo, padded rows (272B stride).
// ---------------------------------------------------------------------------
#define BSTRIDE 272

__global__ void k_w2prep(const float* __restrict__ W2) {
    int t = blockIdx.x * 256 + threadIdx.x;   // 0..4095
    int n = t >> 5;
    int k = (t & 31) * 4;
    float4 f;
    f.x = W2[(k + 0) * 128 + n];
    f.y = W2[(k + 1) * 128 + n];
    f.z = W2[(k + 2) * 128 + n];
    f.w = W2[(k + 3) * 128 + n];
    u64 hp, lp;
    split4(f, hp, lp);
    *(u64*)(g_w2hi + n * BSTRIDE + k * 2) = hp;
    *(u64*)(g_w2lo + n * BSTRIDE + k * 2) = lp;
}

// ---------------------------------------------------------------------------
// K3: bf16 mma.sync h_two kernel + fused g2 partials.
// 4096 blocks x 256 threads. bid -> j = bid&511, chunk c=bid>>9: s=c>>2, q=c&3.
// Tile = 64 rows (senders i = s*256+q*64 .. +63, fixed receiver j) x 128 cols.
// Global row of tile-row t: (ibase+t)*512 + j  -> offset (ibase+t)*65536 + j*128.
// D = Ahi*Whi + Ahi*Wlo + Alo*Whi; epilogue: out = (hi+lo + gain*tanh(D+b2))*rsqrt2.
// g2 partial: column sum of A tile -> g_g2p[q][s][j][:].
// ---------------------------------------------------------------------------
#define S_AHI 0
#define S_ALO 17408
#define S_WHI 34816
#define S_WLO 69632
#define S_RED 104448
#define SMEM_TWO 108544

__global__ void __launch_bounds__(256, 2)
k_two(const float* __restrict__ h_two,
      const float* __restrict__ b2,
      float* __restrict__ out_two) {
    extern __shared__ char smem[];
    u32 sb = smem_u32(smem);
    int tid = threadIdx.x;
    int lane = tid & 31;
    int w = tid >> 5;

    int j = blockIdx.x & 511;
    int ch = blockIdx.x >> 9;      // 0..7
    int s = ch >> 2;
    int q = ch & 3;
    int ibase = s * 256 + q * 64;

    // stage W2T hi/lo images: 2176 uint4 each
    {
        const uint4* wh = (const uint4*)g_w2hi;
        const uint4* wl = (const uint4*)g_w2lo;
        uint4* dh = (uint4*)(smem + S_WHI);
        uint4* dl = (uint4*)(smem + S_WLO);
        for (int idx = tid; idx < 2176; idx += 256) {
            dh[idx] = wh[idx];
            dl[idx] = wl[idx];
        }
    }
    // stage A tile: split fp32 -> bf16 hi/lo + accumulate column sums
    {
        int rr = tid >> 5;          // 0..7
        int kc = tid & 31;          // k-quad
        const float* base = h_two + (size_t)(ibase + rr) * 65536 + (size_t)j * 128 + kc * 4;
        float4 csum = make_float4(0.f, 0.f, 0.f, 0.f);
#pragma unroll
        for (int it = 0; it < 8; it++) {
            int row = rr + it * 8;
            float4 v = *(const float4*)(base + (size_t)it * 8 * 65536);
            csum.x += v.x; csum.y += v.y; csum.z += v.z; csum.w += v.w;
            u64 hp, lp;
            split4(v, hp, lp);
            *(u64*)(smem + S_AHI + row * BSTRIDE + kc * 8) = hp;
            *(u64*)(smem + S_ALO + row * BSTRIDE + kc * 8) = lp;
        }
        *(float4*)(smem + S_RED + (rr * 32 + kc) * 16) = csum;
    }
    __syncthreads();

    // g2 partial: threads 0..127 reduce 8 rr-partials for column p=tid
    if (tid < 128) {
        int p = tid;
        float sum = 0.f;
#pragma unroll
        for (int rr = 0; rr < 8; rr++)
            sum += *(const float*)(smem + S_RED + (rr * 32 + (p >> 2)) * 16 + (p & 3) * 4);
        g_g2p[(size_t)q * 131072 + (size_t)s * 65536 + (size_t)j * 128 + p] = sum;
    }

    int mw = w & 1;       // m-block: rows mw*32
    int nw = w >> 1;      // n-block: cols nw*32

    u32 a_off = (u32)((mw * 32 + (lane & 15)) * BSTRIDE + ((lane >> 4) << 4));
    u32 b_off = (u32)((((lane & 7) + ((lane >> 4) << 3)) * BSTRIDE) + (((lane >> 3) & 1) << 4));

    float acc[2][4][4];
#pragma unroll
    for (int mi = 0; mi < 2; mi++)
#pragma unroll
        for (int nt = 0; nt < 4; nt++)
#pragma unroll
            for (int c = 0; c < 4; c++) acc[mi][nt][c] = 0.f;

#pragma unroll
    for (int pass = 0; pass < 3; pass++) {
        u32 Ab = sb + (pass < 2 ? S_AHI : S_ALO) + a_off;
        u32 Bb = sb + (pass == 1 ? S_WLO : S_WHI) + (u32)(nw * 32 * BSTRIDE) + b_off;
#pragma unroll
        for (int ks = 0; ks < 8; ks++) {
            u32 a0[4], a1[4], b0[4], b1[4];
            ldsm4(a0, Ab + ks * 32);
            ldsm4(a1, Ab + 16 * BSTRIDE + ks * 32);
            ldsm4(b0, Bb + ks * 32);
            ldsm4(b1, Bb + 16 * BSTRIDE + ks * 32);
            mma16816(acc[0][0], a0, b0);
            mma16816(acc[0][1], a0, b0 + 2);
            mma16816(acc[0][2], a0, b1);
            mma16816(acc[0][3], a0, b1 + 2);
            mma16816(acc[1][0], a1, b0);
            mma16816(acc[1][1], a1, b0 + 2);
            mma16816(acc[1][2], a1, b1);
            mma16816(acc[1][3], a1, b1 + 2);
        }
    }

    // epilogue: out = (A + GAIN*tanh(D + b2)) * RSQRT2; A = hi + lo from smem
    int col0 = nw * 32 + (lane & 3) * 2;
    float2 bz[4];
#pragma unroll
    for (int nt = 0; nt < 4; nt++) bz[nt] = *(const float2*)(b2 + col0 + nt * 8);

#pragma unroll
    for (int mi = 0; mi < 2; mi++) {
#pragma unroll
        for (int half = 0; half < 2; half++) {
            int rt = mw * 32 + mi * 16 + half * 8 + (lane >> 2);
            float* orow = out_two + ((size_t)(ibase + rt) * 512 + j) * 128;
#pragma unroll
            for (int nt = 0; nt < 4; nt++) {
                int c = col0 + nt * 8;
                u32 hw = *(const u32*)(smem + S_AHI + rt * BSTRIDE + c * 2);
                u32 lw = *(const u32*)(smem + S_ALO + rt * BSTRIDE + c * 2);
                float a0 = __uint_as_float(hw << 16) + __uint_as_float(lw << 16);
                float a1 = __uint_as_float(hw & 0xFFFF0000u) + __uint_as_float(lw & 0xFFFF0000u);
                float d0 = acc[mi][nt][half * 2 + 0] + bz[nt].x;
                float d1 = acc[mi][nt][half * 2 + 1] + bz[nt].y;
                float2 o;
                o.x = (a0 + GAIN * tanh_fast(d0)) * RSQRT2;
                o.y = (a1 + GAIN * tanh_fast(d1)) * RSQRT2;
                *(float2*)(orow + c) = o;
            }
        }
    }
}

// ---------------------------------------------------------------------------
extern "C" void kernel_launch(void* const* d_in, const int* in_sizes, int n_in,
                              void* d_out, int out_size) {
    const float* h_one = (const float*)d_in[0];
    const float* h_two = (const float*)d_in[1];
    const float* W1    = (const float*)d_in[2];
    const float* b1    = (const float*)d_in[3];
    const float* Wg    = (const float*)d_in[4];
    const float* W2    = (const float*)d_in[5];
    const float* b2    = (const float*)d_in[6];

    float* out_one = (float*)d_out;
    float* out_two = (float*)d_out + 512 * 256;

    cudaFuncSetAttribute(k_two, cudaFuncAttributeMaxDynamicSharedMemorySize, SMEM_TWO);

    k_w2prep<<<16, 256>>>(W2);
    k_g1<<<2, 256>>>(h_one);
    k_gt<<<1, 256>>>(Wg, b1);
    k_two<<<4096, 256, SMEM_TWO>>>(h_two, b2, out_two);
    k_g2c<<<128, 256>>>();
    k_one<<<256, 256>>>(h_one, W1, out_one);
}

// round 7
// speedup vs baseline: 2.3381x; 1.3747x over previous
#include <cuda_runtime.h>
#include <cuda_fp16.h>
#include <cstdint>

// ---------------------------------------------------------------------------
// FermiLayer: N=512 (256 up / 256 dn), SINGLE=256, PAIR=128
// inputs: [0] h_one (512,256) [1] h_two (512,512,128) [2] W1 (512,256)
//         [3] b1 (256) [4] Wg (512,256) [5] W2 (128,128) [6] b2 (128)
// output: [h_one_out | h_two_out] fp32
// k_two: fp16 mma.sync 2-pass exact-A split: D = Ah*Wh + Al*Wh = A*Wh.
// Only error is A*(W-Wh) ~ 2^-11 rel -> out rel err ~1e-4.
// g2 column-sum partials fused into k_two; k_one folds the combine.
// ---------------------------------------------------------------------------

#define GAIN    1.5927812698663017f
#define RSQRT2  0.7071067811865475f
#define INV256  0.00390625f

typedef unsigned long long u64;
typedef unsigned int u32;

// scratch (__device__ globals: allocation-free rule)
__device__ float g_g2p[4 * 2 * 512 * 128];  // [q][s][j][p] partial sums (64 i each)
__device__ float g_g1[512];
__device__ float g_gt[256];
// W2^T fp16 in padded [n][k] layout (row stride 272B)
__device__ __align__(16) unsigned char g_w2h[35840];

__device__ __forceinline__ float tanh_fast(float x) {
    float y;
    asm("tanh.approx.f32 %0, %1;" : "=f"(y) : "f"(x));
    return y;
}
__device__ __forceinline__ u32 smem_u32(const void* p) {
    u32 a;
    asm("{ .reg .u64 t; cvta.to.shared.u64 t, %1; cvt.u32.u64 %0, t; }" : "=r"(a) : "l"(p));
    return a;
}
__device__ __forceinline__ void ldsm4(u32* r, u32 addr) {
    asm volatile("ldmatrix.sync.aligned.m8n8.x4.shared.b16 {%0,%1,%2,%3}, [%4];"
                 : "=r"(r[0]), "=r"(r[1]), "=r"(r[2]), "=r"(r[3]) : "r"(addr));
}
__device__ __forceinline__ void mma16816(float* c, const u32* a, const u32* b) {
    asm volatile(
        "mma.sync.aligned.m16n8k16.row.col.f32.f16.f16.f32 "
        "{%0,%1,%2,%3}, {%4,%5,%6,%7}, {%8,%9}, {%0,%1,%2,%3};"
        : "+f"(c[0]), "+f"(c[1]), "+f"(c[2]), "+f"(c[3])
        : "r"(a[0]), "r"(a[1]), "r"(a[2]), "r"(a[3]), "r"(b[0]), "r"(b[1]));
}
// split two floats into fp16 hi pair + fp16 lo pair (lo = residual)
__device__ __forceinline__ void split2h(float e0, float e1, u32& hp, u32& lp) {
    __half2 h = __float22half2_rn(make_float2(e0, e1));
    float2 hf = __half22float2(h);
    __half2 l = __float22half2_rn(make_float2(e0 - hf.x, e1 - hf.y));
    hp = *(u32*)&h;
    lp = *(u32*)&l;
}
__device__ __forceinline__ void split4h(const float4& v, u64& hp, u64& lp) {
    u32 h0, l0, h1, l1;
    split2h(v.x, v.y, h0, l0);
    split2h(v.z, v.w, h1, l1);
    hp = (u64)h0 | ((u64)h1 << 32);
    lp = (u64)l0 | ((u64)l1 << 32);
}

// ---------------------------------------------------------------------------
__global__ void k_g1(const float* __restrict__ h_one) {
    int s = blockIdx.x, c = threadIdx.x;
    const float* p = h_one + (size_t)s * 65536 + c;
    float sum = 0.f;
#pragma unroll 8
    for (int r = 0; r < 256; r++) sum += p[r * 256];
    g_g1[s * 256 + c] = sum * INV256;
}

__global__ void k_gt(const float* __restrict__ Wg, const float* __restrict__ b1) {
    __shared__ float s_g1[512];
    int c = threadIdx.x;
    s_g1[c] = g_g1[c];
    s_g1[c + 256] = g_g1[c + 256];
    __syncthreads();
    float acc = b1[c];
#pragma unroll 4
    for (int kb = 0; kb < 64; kb++) {
        float w[8];
#pragma unroll
        for (int i = 0; i < 8; i++) w[i] = Wg[(kb * 8 + i) * 256 + c];
#pragma unroll
        for (int i = 0; i < 8; i++) acc += s_g1[kb * 8 + i] * w[i];
    }
    g_gt[c] = acc;
}

// ---------------------------------------------------------------------------
// K2: h_one path (256 blocks x 256 threads, 2 rows/block).
// Folds the g2 partial combine (4 chunks) into staging.
// ---------------------------------------------------------------------------
__global__ void __launch_bounds__(256)
k_one(const float* __restrict__ h_one,
      const float* __restrict__ W1,
      float* __restrict__ out_one) {
    __shared__ float s_in[1024];
    int tid = threadIdx.x;
    int r0 = blockIdx.x * 2;
#pragma unroll
    for (int i = 0; i < 4; i++) {
        int e = tid + i * 256;
        int k = e >> 1;
        int r = e & 1;
        int n = r0 + r;
        float v;
        if (k < 256) {
            v = h_one[n * 256 + k];
        } else {
            int sp = (k < 384) ? 0 : 1;
            int p = k - 256 - sp * 128;
            size_t base = (size_t)sp * 65536 + (size_t)n * 128 + p;
            v = (g_g2p[base] + g_g2p[base + 131072] +
                 g_g2p[base + 262144] + g_g2p[base + 393216]) * INV256;
        }
        s_in[k * 2 + r] = v;
    }
    __syncthreads();
    const float2* s2 = (const float2*)s_in;
    int c = tid;
    float acc0 = 0.f, acc1 = 0.f;
#pragma unroll 4
    for (int kb = 0; kb < 64; kb++) {
        float w[8];
#pragma unroll
        for (int i = 0; i < 8; i++) w[i] = W1[(kb * 8 + i) * 256 + c];
#pragma unroll
        for (int i = 0; i < 8; i++) {
            float2 a = s2[kb * 8 + i];
            acc0 += a.x * w[i];
            acc1 += a.y * w[i];
        }
    }
    float gt = g_gt[c];
    out_one[r0 * 256 + c]       = (s_in[c * 2]     + GAIN * tanh_fast((acc0 + gt) * RSQRT2)) * RSQRT2;
    out_one[(r0 + 1) * 256 + c] = (s_in[c * 2 + 1] + GAIN * tanh_fast((acc1 + gt) * RSQRT2)) * RSQRT2;
}

// ---------------------------------------------------------------------------
// W2 prep: W2T[n][k] = fp16(W2[k][n]), padded rows (272B stride).
// ---------------------------------------------------------------------------
#define BSTRIDE 272

__global__ void k_w2prep(const float* __restrict__ W2) {
    int t = blockIdx.x * 256 + threadIdx.x;   // 0..4095
    int n = t >> 5;
    int k = (t & 31) * 4;
    __half2 h0 = __float22half2_rn(make_float2(W2[(k + 0) * 128 + n], W2[(k + 1) * 128 + n]));
    __half2 h1 = __float22half2_rn(make_float2(W2[(k + 2) * 128 + n], W2[(k + 3) * 128 + n]));
    u64 hp = (u64)(*(u32*)&h0) | ((u64)(*(u32*)&h1) << 32);
    *(u64*)(g_w2h + n * BSTRIDE + k * 2) = hp;
}

// ---------------------------------------------------------------------------
// K3: fp16 mma.sync h_two kernel + fused g2 partials. 4096 blocks x 256 thr.
// bid -> j = bid&511, chunk ch=bid>>9: s=ch>>2, q=ch&3; rows = 64 senders.
// D = Ah*Wh + Al*Wh (= A*Wh); epilogue: out = (Ah+Al + gain*tanh(D+b2))*rsqrt2.
// ---------------------------------------------------------------------------
#define S_AHI 0
#define S_ALO 17408
#define S_WHI 34816
#define S_RED 69632
#define SMEM_TWO 73728

__global__ void __launch_bounds__(256, 2)
k_two(const float* __restrict__ h_two,
      const float* __restrict__ b2,
      float* __restrict__ out_two) {
    extern __shared__ char smem[];
    u32 sb = smem_u32(smem);
    int tid = threadIdx.x;
    int lane = tid & 31;
    int w = tid >> 5;

    int j = blockIdx.x & 511;
    int ch = blockIdx.x >> 9;      // 0..7
    int s = ch >> 2;
    int q = ch & 3;
    int ibase = s * 256 + q * 64;

    // stage W2T fp16 image: 2176 uint4
    {
        const uint4* wh = (const uint4*)g_w2h;
        uint4* dh = (uint4*)(smem + S_WHI);
        for (int idx = tid; idx < 2176; idx += 256) dh[idx] = wh[idx];
    }
    // stage A tile: split fp32 -> fp16 hi/lo + accumulate column sums
    {
        int rr = tid >> 5;          // 0..7
        int kc = tid & 31;          // k-quad
        const float* base = h_two + (size_t)(ibase + rr) * 65536 + (size_t)j * 128 + kc * 4;
        float4 csum = make_float4(0.f, 0.f, 0.f, 0.f);
#pragma unroll
        for (int it = 0; it < 8; it++) {
            int row = rr + it * 8;
            float4 v = *(const float4*)(base + (size_t)it * 8 * 65536);
            csum.x += v.x; csum.y += v.y; csum.z += v.z; csum.w += v.w;
            u64 hp, lp;
            split4h(v, hp, lp);
            *(u64*)(smem + S_AHI + row * BSTRIDE + kc * 8) = hp;
            *(u64*)(smem + S_ALO + row * BSTRIDE + kc * 8) = lp;
        }
        *(float4*)(smem + S_RED + (rr * 32 + kc) * 16) = csum;
    }
    __syncthreads();

    // g2 partial: threads 0..127 reduce 8 rr-partials for column p=tid
    if (tid < 128) {
        int p = tid;
        float sum = 0.f;
#pragma unroll
        for (int rr = 0; rr < 8; rr++)
            sum += *(const float*)(smem + S_RED + (rr * 32 + (p >> 2)) * 16 + (p & 3) * 4);
        g_g2p[(size_t)q * 131072 + (size_t)s * 65536 + (size_t)j * 128 + p] = sum;
    }

    int mw = w & 1;       // m-block: rows mw*32
    int nw = w >> 1;      // n-block: cols nw*32

    u32 a_off = (u32)((mw * 32 + (lane & 15)) * BSTRIDE + ((lane >> 4) << 4));
    u32 b_off = (u32)((((lane & 7) + ((lane >> 4) << 3)) * BSTRIDE) + (((lane >> 3) & 1) << 4));

    float acc[2][4][4];
#pragma unroll
    for (int mi = 0; mi < 2; mi++)
#pragma unroll
        for (int nt = 0; nt < 4; nt++)
#pragma unroll
            for (int c = 0; c < 4; c++) acc[mi][nt][c] = 0.f;

#pragma unroll
    for (int pass = 0; pass < 2; pass++) {
        u32 Ab = sb + (pass ? S_ALO : S_AHI) + a_off;
        u32 Bb = sb + S_WHI + (u32)(nw * 32 * BSTRIDE) + b_off;
#pragma unroll
        for (int ks = 0; ks < 8; ks++) {
            u32 a0[4], a1[4], b0[4], b1[4];
            ldsm4(a0, Ab + ks * 32);
            ldsm4(a1, Ab + 16 * BSTRIDE + ks * 32);
            ldsm4(b0, Bb + ks * 32);
            ldsm4(b1, Bb + 16 * BSTRIDE + ks * 32);
            mma16816(acc[0][0], a0, b0);
            mma16816(acc[0][1], a0, b0 + 2);
            mma16816(acc[0][2], a0, b1);
            mma16816(acc[0][3], a0, b1 + 2);
            mma16816(acc[1][0], a1, b0);
            mma16816(acc[1][1], a1, b0 + 2);
            mma16816(acc[1][2], a1, b1);
            mma16816(acc[1][3], a1, b1 + 2);
        }
    }

    // epilogue: out = (A + GAIN*tanh(D + b2)) * RSQRT2; A = hi + lo from smem
    int col0 = nw * 32 + (lane & 3) * 2;
    float2 bz[4];
#pragma unroll
    for (int nt = 0; nt < 4; nt++) bz[nt] = *(const float2*)(b2 + col0 + nt * 8);

#pragma unroll
    for (int mi = 0; mi < 2; mi++) {
#pragma unroll
        for (int half = 0; half < 2; half++) {
            int rt = mw * 32 + mi * 16 + half * 8 + (lane >> 2);
            float* orow = out_two + ((size_t)(ibase + rt) * 512 + j) * 128;
#pragma unroll
            for (int nt = 0; nt < 4; nt++) {
                int c = col0 + nt * 8;
                __half2 hh = *(const __half2*)(smem + S_AHI + rt * BSTRIDE + c * 2);
                __half2 ll = *(const __half2*)(smem + S_ALO + rt * BSTRIDE + c * 2);
                float2 hf = __half22float2(hh);
                float2 lf = __half22float2(ll);
                float d0 = acc[mi][nt][half * 2 + 0] + bz[nt].x;
                float d1 = acc[mi][nt][half * 2 + 1] + bz[nt].y;
                float2 o;
                o.x = (hf.x + lf.x + GAIN * tanh_fast(d0)) * RSQRT2;
                o.y = (hf.y + lf.y + GAIN * tanh_fast(d1)) * RSQRT2;
                *(float2*)(orow + c) = o;
            }
        }
    }
}

// ---------------------------------------------------------------------------
extern "C" void kernel_launch(void* const* d_in, const int* in_sizes, int n_in,
                              void* d_out, int out_size) {
    const float* h_one = (const float*)d_in[0];
    const float* h_two = (const float*)d_in[1];
    const float* W1    = (const float*)d_in[2];
    const float* b1    = (const float*)d_in[3];
    const float* Wg    = (const float*)d_in[4];
    const float* W2    = (const float*)d_in[5];
    const float* b2    = (const float*)d_in[6];

    float* out_one = (float*)d_out;
    float* out_two = (float*)d_out + 512 * 256;

    cudaFuncSetAttribute(k_two, cudaFuncAttributeMaxDynamicSharedMemorySize, SMEM_TWO);

    k_w2prep<<<16, 256>>>(W2);
    k_g1<<<2, 256>>>(h_one);
    k_gt<<<1, 256>>>(Wg, b1);
    k_two<<<4096, 256, SMEM_TWO>>>(h_two, b2, out_two);
    k_one<<<256, 256>>>(h_one, W1, out_one);
}